// round 9
// baseline (speedup 1.0000x reference)
#include <cuda_runtime.h>
#include <math.h>

#define NQ 20
#define NSTATE (1u << NQ)
#define NPAIR 2   // batch pairs (B=4 -> 2 pairs packed into f32x2 lanes)
typedef unsigned long long ull;

// Scratch state, batch-pair packed: element = ulonglong2{ R=(re_b0,re_b1), I=(im_b0,im_b1) }
__device__ __align__(16) ulonglong2 g_bufA[(size_t)NPAIR << NQ];
__device__ __align__(16) ulonglong2 g_bufB[(size_t)NPAIR << NQ];
// Precomputed per (layer, state-bit): RX (cos(t/2), sin(t/2)) and RZ half-angles
__device__ float2 g_cs[4 * 32];
__device__ float  g_hz[4 * 32];

struct P2 { ull R, I; };

__device__ __forceinline__ ull pk2(float lo, float hi) {
    ull r; asm("mov.b64 %0,{%1,%2};" : "=l"(r) : "f"(lo), "f"(hi)); return r;
}
__device__ __forceinline__ void upk2(ull v, float& lo, float& hi) {
    asm("mov.b64 {%0,%1},%2;" : "=f"(lo), "=f"(hi) : "l"(v));
}
__device__ __forceinline__ ull dup2(float x) { return pk2(x, x); }
__device__ __forceinline__ ull f2mul(ull a, ull b) {
    ull r; asm("mul.rn.f32x2 %0,%1,%2;" : "=l"(r) : "l"(a), "l"(b)); return r;
}
__device__ __forceinline__ ull f2fma(ull a, ull b, ull c) {
    ull r; asm("fma.rn.f32x2 %0,%1,%2,%3;" : "=l"(r) : "l"(a), "l"(b), "l"(c)); return r;
}

// RX butterfly: v0' = c v0 - i s v1 ; v1' = -i s v0 + c v1
__device__ __forceinline__ void rx_bfly(P2& a, P2& b, ull cc, ull ss, ull ns) {
    ull r0 = f2fma(a.R, cc, f2mul(b.I, ss));
    ull i0 = f2fma(a.I, cc, f2mul(b.R, ns));
    ull r1 = f2fma(b.R, cc, f2mul(a.I, ss));
    ull i1 = f2fma(b.I, cc, f2mul(a.R, ns));
    a.R = r0; a.I = i0; b.R = r1; b.I = i1;
}
__device__ __forceinline__ void h_bfly(P2& a, P2& b, ull rr, ull nr) {
    ull r0 = f2fma(a.R, rr, f2mul(b.R, rr));
    ull i0 = f2fma(a.I, rr, f2mul(b.I, rr));
    ull r1 = f2fma(a.R, rr, f2mul(b.R, nr));
    ull i1 = f2fma(a.I, rr, f2mul(b.I, nr));
    a.R = r0; a.I = i0; b.R = r1; b.I = i1;
}
// v *= (fr + i fi)
__device__ __forceinline__ void ph_apply(P2& a, ull cc, ull ss, ull ns) {
    ull r = f2fma(a.R, cc, f2mul(a.I, ns));
    ull i = f2fma(a.I, cc, f2mul(a.R, ss));
    a.R = r; a.I = i;
}

// 16-element register arrays: radix-16 rounds, stage K pairs differ in bit K.
template<int K> __device__ __forceinline__ void rx_stage16(P2* v, float2 cs) {
    ull cc = dup2(cs.x), ss = dup2(cs.y), ns = dup2(-cs.y);
#pragma unroll
    for (int p = 0; p < 8; ++p) {
        int i0 = ((p >> K) << (K + 1)) | (p & ((1 << K) - 1));
        rx_bfly(v[i0], v[i0 | (1 << K)], cc, ss, ns);
    }
}
template<int K> __device__ __forceinline__ void h_stage16(P2* v) {
    const float r2 = 0.7071067811865476f;
    ull rr = dup2(r2), nr = dup2(-r2);
#pragma unroll
    for (int p = 0; p < 8; ++p) {
        int i0 = ((p >> K) << (K + 1)) | (p & ((1 << K) - 1));
        h_bfly(v[i0], v[i0 | (1 << K)], rr, nr);
    }
}
__device__ __forceinline__ void h4_16(P2* v) {
    h_stage16<0>(v); h_stage16<1>(v); h_stage16<2>(v); h_stage16<3>(v);
}
__device__ __forceinline__ void rx4_16(P2* v, int l, int b0) {
    rx_stage16<0>(v, g_cs[l * 32 + b0 + 0]);
    rx_stage16<1>(v, g_cs[l * 32 + b0 + 1]);
    rx_stage16<2>(v, g_cs[l * 32 + b0 + 2]);
    rx_stage16<3>(v, g_cs[l * 32 + b0 + 3]);
}

// smem swizzle: distinct (sw&7) within each 8-lane phase for all access patterns
__device__ __forceinline__ unsigned sw(unsigned t) { return t ^ ((t >> 4) & 15u); }

// Setup: per (layer, bit) RX coefs + RZ half angles (theta index = l*20 + (19-bit))
__global__ void k_setup(const float* __restrict__ thx, const float* __restrict__ thz) {
    int i = threadIdx.x;
    if (i < 80) {
        int l = i / 20, q = i % 20, bit = 19 - q;
        float s, c; sincosf(0.5f * thx[i], &s, &c);
        g_cs[l * 32 + bit] = make_float2(c, s);
        g_hz[l * 32 + bit] = 0.5f * thz[i];
    }
}

// ---------------------------------------------------------------------------
// LOW pass: tile = state bits 0..11 (4096 packed elements, 64KB dynamic smem),
// 256 thr x 16 elems, 3 rounds: bits 0..3 | 4..7 | 8..11.
// HG: Hadamards; else RX layer l. FO: final gray-decode scatter of REAL parts.
// src: 1 -> in=B,out=A ; 0 -> in=A,out=B.
// ---------------------------------------------------------------------------
template<bool HG, bool PL, bool FO>
__global__ void __launch_bounds__(256) k_low(
    const float* __restrict__ re, const float* __restrict__ im,
    int src, float* __restrict__ fout, int l)
{
    extern __shared__ ulonglong2 ts[];
    const unsigned u = threadIdx.x, blk = blockIdx.x;
    const unsigned pair = blk >> 8, base = (blk & 255u) << 12;   // bits 12..19
    const size_t poff = (size_t)pair << NQ;

    const ulonglong2* __restrict__ in = (src & 1) ? g_bufB : g_bufA;
    ulonglong2* __restrict__ out = (src & 1) ? g_bufA : g_bufB;

    P2 v[16];
    // R0: e = bits 0..3
    {
        const unsigned t0 = u << 4;
        if (PL) {
            size_t b0 = ((size_t)(2 * pair) << NQ) + base + t0;
            const float4* r0p = (const float4*)(re + b0);
            const float4* r1p = (const float4*)(re + b0 + NSTATE);
            const float4* i0p = (const float4*)(im + b0);
            const float4* i1p = (const float4*)(im + b0 + NSTATE);
#pragma unroll
            for (int j = 0; j < 4; ++j) {
                float4 ra = r0p[j], rb = r1p[j], ia = i0p[j], ib = i1p[j];
                v[4 * j + 0].R = pk2(ra.x, rb.x); v[4 * j + 0].I = pk2(ia.x, ib.x);
                v[4 * j + 1].R = pk2(ra.y, rb.y); v[4 * j + 1].I = pk2(ia.y, ib.y);
                v[4 * j + 2].R = pk2(ra.z, rb.z); v[4 * j + 2].I = pk2(ia.z, ib.z);
                v[4 * j + 3].R = pk2(ra.w, rb.w); v[4 * j + 3].I = pk2(ia.w, ib.w);
            }
        } else {
#pragma unroll
            for (int j = 0; j < 16; ++j) {
                ulonglong2 w = in[poff + base + t0 + j]; v[j].R = w.x; v[j].I = w.y;
            }
        }
        if (HG) h4_16(v); else rx4_16(v, l, 0);
#pragma unroll
        for (int e = 0; e < 16; ++e) ts[sw(t0 | e)] = make_ulonglong2(v[e].R, v[e].I);
    }
    __syncthreads();
    // R1: e = bits 4..7 ; thread: bits 0..3 = u&15, bits 8..11 = u>>4
    {
        const unsigned tb = ((u >> 4) << 8) | (u & 15u);
#pragma unroll
        for (int e = 0; e < 16; ++e) { ulonglong2 w = ts[sw(tb | (e << 4))]; v[e].R = w.x; v[e].I = w.y; }
        if (HG) h4_16(v); else rx4_16(v, l, 4);
#pragma unroll
        for (int e = 0; e < 16; ++e) ts[sw(tb | (e << 4))] = make_ulonglong2(v[e].R, v[e].I);
    }
    __syncthreads();
    // R2: e = bits 8..11 ; thread u = bits 0..7
    {
#pragma unroll
        for (int e = 0; e < 16; ++e) { ulonglong2 w = ts[sw((e << 8) | u)]; v[e].R = w.x; v[e].I = w.y; }
        if (HG) h4_16(v); else rx4_16(v, l, 8);
        if (FO) {
            // out[i] = Re(state[i ^ (i>>1)])  <=>  fout[graydecode(s)] = Re(state[s])
#pragma unroll
            for (int e = 0; e < 16; ++e) {
                unsigned s = base | ((unsigned)e << 8) | u;
                unsigned d = s; d ^= d >> 1; d ^= d >> 2; d ^= d >> 4; d ^= d >> 8; d ^= d >> 16;
                float lo, hi; upk2(v[e].R, lo, hi);
                fout[((size_t)(2 * pair) << NQ) + d] = lo;
                fout[((size_t)(2 * pair + 1) << NQ) + d] = hi;
            }
        } else {
#pragma unroll
            for (int e = 0; e < 16; ++e)
                out[poff + base + ((unsigned)e << 8) + u] = make_ulonglong2(v[e].R, v[e].I);
        }
    }
}

// ---------------------------------------------------------------------------
// HIGH first (layer 0): H(12..19) + RZ0(all) + RX0(12..19) in 2 rounds.
// Tile = bits {0..3} U {12..19} (4096, 64KB). Block fixes bits 4..11.
// R0: thread = c(bits0..3)|r(bits16..19), e = bits 12..15: H, phase(0..15), RX.
// R1: thread = c|q(bits12..15), e = bits 16..19: H, phase(16..19), RX, store.
// ---------------------------------------------------------------------------
__global__ void __launch_bounds__(256) k_highf(int src, int l)
{
    extern __shared__ ulonglong2 ts[];
    __shared__ float2 zf0[16], zf1[16];
    __shared__ float hz_s[12];
    const unsigned u = threadIdx.x, blk = blockIdx.x;
    const unsigned pair = blk >> 8, mid = (blk & 255u) << 4;   // bits 4..11
    const size_t poff = (size_t)pair << NQ;

    const ulonglong2* __restrict__ in = (src & 1) ? g_bufB : g_bufA;
    ulonglong2* __restrict__ out = (src & 1) ? g_bufA : g_bufB;

    if (u < 12) hz_s[u] = g_hz[l * 32 + u];
    if (u < 32) {
        int tb = u >> 4, e = u & 15;
        float ph = 0.f;
#pragma unroll
        for (int k = 0; k < 4; ++k) {
            float t = g_hz[l * 32 + 12 + tb * 4 + k];
            ph += ((e >> k) & 1) ? t : -t;
        }
        float sp, cp; sincosf(ph, &sp, &cp);
        if (tb == 0) zf0[e] = make_float2(cp, sp); else zf1[e] = make_float2(cp, sp);
    }
    __syncthreads();

    P2 v[16];
    const unsigned c = u & 15u, r = u >> 4;

    // R0: e = bits 12..15
    {
        const unsigned gfl = mid | c;                 // bits 0..11
        const unsigned gf = (r << 16) | gfl;
#pragma unroll
        for (int e = 0; e < 16; ++e) {
            ulonglong2 w = in[poff + (gf | ((unsigned)e << 12))]; v[e].R = w.x; v[e].I = w.y;
        }
        h4_16(v);
        float ph = 0.f;
#pragma unroll
        for (int b = 0; b < 12; ++b) ph += ((gfl >> b) & 1u) ? hz_s[b] : -hz_s[b];
        float sp, cp; sincosf(ph, &sp, &cp);
#pragma unroll
        for (int e = 0; e < 16; ++e) {
            float2 z = zf0[e];
            float fr = fmaf(cp, z.x, -sp * z.y);
            float fi = fmaf(cp, z.y, sp * z.x);
            ph_apply(v[e], dup2(fr), dup2(fi), dup2(-fi));
        }
        rx4_16(v, l, 12);
        const unsigned tb = (r << 8) | c;
#pragma unroll
        for (int e = 0; e < 16; ++e) ts[sw(tb | (e << 4))] = make_ulonglong2(v[e].R, v[e].I);
    }
    __syncthreads();
    // R1: e = bits 16..19 ; thread: c = u&15, q = u>>4 (bits 12..15)
    {
        const unsigned q = u >> 4;
        const unsigned tb = (q << 4) | c;
#pragma unroll
        for (int e = 0; e < 16; ++e) { ulonglong2 w = ts[sw(tb | (e << 8))]; v[e].R = w.x; v[e].I = w.y; }
        h4_16(v);
#pragma unroll
        for (int e = 0; e < 16; ++e) {
            float2 z = zf1[e];
            ph_apply(v[e], dup2(z.x), dup2(z.y), dup2(-z.y));
        }
        rx4_16(v, l, 16);
        const unsigned gl = mid | c | (q << 12);
#pragma unroll
        for (int e = 0; e < 16; ++e)
            out[poff + (gl | ((unsigned)e << 16))] = make_ulonglong2(v[e].R, v[e].I);
    }
}

// ---------------------------------------------------------------------------
// HIGH mid (layers 1..3): gray gather (fused CNOT chain), RZ(all), RX(12..19).
// ---------------------------------------------------------------------------
__global__ void __launch_bounds__(256) k_highm(int src, int l)
{
    extern __shared__ ulonglong2 ts[];
    __shared__ float2 zf0[16];
    __shared__ float hz_s[20];
    const unsigned u = threadIdx.x, blk = blockIdx.x;
    const unsigned pair = blk >> 8, mid = (blk & 255u) << 4;   // bits 4..11
    const size_t poff = (size_t)pair << NQ;

    const ulonglong2* __restrict__ in = (src & 1) ? g_bufB : g_bufA;
    ulonglong2* __restrict__ out = (src & 1) ? g_bufA : g_bufB;

    if (u < 20) hz_s[u] = g_hz[l * 32 + u];
    if (u < 16) {
        float ph = 0.f;
#pragma unroll
        for (int k = 0; k < 4; ++k) {
            float t = g_hz[l * 32 + 12 + k];
            ph += ((u >> k) & 1u) ? t : -t;
        }
        float sp, cp; sincosf(ph, &sp, &cp);
        zf0[u] = make_float2(cp, sp);
    }
    __syncthreads();

    P2 v[16];
    const unsigned c = u & 15u, r = u >> 4;

    // R0: e = bits 12..15 : gray gather + RZ(all) + RX(12..15)
    {
        const unsigned gf = (r << 16) | mid | c;
        float ph = 0.f;
#pragma unroll
        for (int b = 0; b < 12; ++b) ph += ((gf >> b) & 1u) ? hz_s[b] : -hz_s[b];
#pragma unroll
        for (int b = 16; b < 20; ++b) ph += ((gf >> b) & 1u) ? hz_s[b] : -hz_s[b];
        float sp, cp; sincosf(ph, &sp, &cp);
#pragma unroll
        for (int e = 0; e < 16; ++e) {
            unsigned g = gf | ((unsigned)e << 12);
            unsigned a = g ^ (g >> 1);               // CNOT chain = binary->gray
            ulonglong2 w = in[poff + a]; v[e].R = w.x; v[e].I = w.y;
            float2 z = zf0[e];
            float fr = fmaf(cp, z.x, -sp * z.y);
            float fi = fmaf(cp, z.y, sp * z.x);
            ph_apply(v[e], dup2(fr), dup2(fi), dup2(-fi));
        }
        rx4_16(v, l, 12);
        const unsigned tb = (r << 8) | c;
#pragma unroll
        for (int e = 0; e < 16; ++e) ts[sw(tb | (e << 4))] = make_ulonglong2(v[e].R, v[e].I);
    }
    __syncthreads();
    // R1: e = bits 16..19 : RX(16..19), store
    {
        const unsigned q = u >> 4;
        const unsigned tb = (q << 4) | c;
#pragma unroll
        for (int e = 0; e < 16; ++e) { ulonglong2 w = ts[sw(tb | (e << 8))]; v[e].R = w.x; v[e].I = w.y; }
        rx4_16(v, l, 16);
        const unsigned gl = mid | c | (q << 12);
#pragma unroll
        for (int e = 0; e < 16; ++e)
            out[poff + (gl | ((unsigned)e << 16))] = make_ulonglong2(v[e].R, v[e].I);
    }
}

extern "C" void kernel_launch(void* const* d_in, const int* in_sizes, int n_in,
                              void* d_out, int out_size) {
    const float *re = nullptr, *im = nullptr, *thx = nullptr, *thz = nullptr;
    for (int i = 0; i < n_in; ++i) {
        if (in_sizes[i] > 1024) {
            if (!re) re = (const float*)d_in[i];
            else if (!im) im = (const float*)d_in[i];
        } else {
            if (!thx) thx = (const float*)d_in[i];
            else if (!thz) thz = (const float*)d_in[i];
        }
    }
    if (!re || !im || !thx || !thz) return;

    const int SMEM = 65536;   // 4096 x 16B tiles
    cudaFuncSetAttribute(k_low<true,  true,  false>, cudaFuncAttributeMaxDynamicSharedMemorySize, SMEM);
    cudaFuncSetAttribute(k_low<false, false, false>, cudaFuncAttributeMaxDynamicSharedMemorySize, SMEM);
    cudaFuncSetAttribute(k_low<false, false, true >, cudaFuncAttributeMaxDynamicSharedMemorySize, SMEM);
    cudaFuncSetAttribute(k_highf, cudaFuncAttributeMaxDynamicSharedMemorySize, SMEM);
    cudaFuncSetAttribute(k_highm, cudaFuncAttributeMaxDynamicSharedMemorySize, SMEM);

    const dim3 gr(NPAIR * 256);
    const int th = 256;

    k_setup<<<1, 128>>>(thx, thz);
    // P1: H bits 0..11, planar -> A
    k_low<true, true, false><<<gr, th, SMEM>>>(re, im, 1, nullptr, 0);
    // P2: H bits 12..19 + RZ0 + RX0(high)    A -> B
    k_highf<<<gr, th, SMEM>>>(0, 0);
    // P3: RX0 bits 0..11                     B -> A
    k_low<false, false, false><<<gr, th, SMEM>>>(nullptr, nullptr, 1, nullptr, 0);
    // P4: gray0 + RZ1 + RX1(high)            A -> B
    k_highm<<<gr, th, SMEM>>>(0, 1);
    // P5: RX1(low)                           B -> A
    k_low<false, false, false><<<gr, th, SMEM>>>(nullptr, nullptr, 1, nullptr, 1);
    // P6: gray1 + RZ2 + RX2(high)            A -> B
    k_highm<<<gr, th, SMEM>>>(0, 2);
    // P7: RX2(low)                           B -> A
    k_low<false, false, false><<<gr, th, SMEM>>>(nullptr, nullptr, 1, nullptr, 2);
    // P8: gray2 + RZ3 + RX3(high)            A -> B
    k_highm<<<gr, th, SMEM>>>(0, 3);
    // P9: RX3(low) + gray3 scatter of REAL parts -> d_out
    k_low<false, false, true><<<gr, th, SMEM>>>(nullptr, nullptr, 1, (float*)d_out, 3);
}

// round 10
// speedup vs baseline: 1.0827x; 1.0827x over previous
#include <cuda_runtime.h>
#include <math.h>

#define NQ 20
#define NSTATE (1u << NQ)
#define NPAIR 2   // batch pairs (B=4 -> 2 pairs packed into f32x2 lanes)
typedef unsigned long long ull;

// Scratch state, batch-pair packed: element = ulonglong2{ R=(re_b0,re_b1), I=(im_b0,im_b1) }
__device__ __align__(16) ulonglong2 g_bufA[(size_t)NPAIR << NQ];
__device__ __align__(16) ulonglong2 g_bufB[(size_t)NPAIR << NQ];
// Precomputed per (layer, state-bit): RX (cos(t/2), sin(t/2)) and RZ half-angles
__device__ float2 g_cs[4 * 32];
__device__ float  g_hz[4 * 32];

struct C2 { ull R, I; };

__device__ __forceinline__ ull pk2(float lo, float hi) {
    ull r; asm("mov.b64 %0,{%1,%2};" : "=l"(r) : "f"(lo), "f"(hi)); return r;
}
__device__ __forceinline__ void upk2(ull v, float& lo, float& hi) {
    asm("mov.b64 {%0,%1},%2;" : "=f"(lo), "=f"(hi) : "l"(v));
}
__device__ __forceinline__ ull dup2(float x) { return pk2(x, x); }
__device__ __forceinline__ ull f2mul(ull a, ull b) {
    ull r; asm("mul.rn.f32x2 %0,%1,%2;" : "=l"(r) : "l"(a), "l"(b)); return r;
}
__device__ __forceinline__ ull f2fma(ull a, ull b, ull c) {
    ull r; asm("fma.rn.f32x2 %0,%1,%2,%3;" : "=l"(r) : "l"(a), "l"(b), "l"(c)); return r;
}

// RX butterfly: v0' = c v0 - i s v1 ; v1' = -i s v0 + c v1
__device__ __forceinline__ void rx_bfly(C2& a, C2& b, ull cc, ull ss, ull ns) {
    ull r0 = f2fma(a.R, cc, f2mul(b.I, ss));
    ull i0 = f2fma(a.I, cc, f2mul(b.R, ns));
    ull r1 = f2fma(b.R, cc, f2mul(a.I, ss));
    ull i1 = f2fma(b.I, cc, f2mul(a.R, ns));
    a.R = r0; a.I = i0; b.R = r1; b.I = i1;
}
__device__ __forceinline__ void h_bfly(C2& a, C2& b, ull rr, ull nr) {
    ull r0 = f2fma(a.R, rr, f2mul(b.R, rr));
    ull i0 = f2fma(a.I, rr, f2mul(b.I, rr));
    ull r1 = f2fma(a.R, rr, f2mul(b.R, nr));
    ull i1 = f2fma(a.I, rr, f2mul(b.I, nr));
    a.R = r0; a.I = i0; b.R = r1; b.I = i1;
}
// v *= (f.x + i f.y)
__device__ __forceinline__ void phf(C2& a, float2 f) {
    ull cc = dup2(f.x), ss = dup2(f.y), ns = dup2(-f.y);
    ull r = f2fma(a.R, cc, f2mul(a.I, ns));
    ull i = f2fma(a.I, cc, f2mul(a.R, ss));
    a.R = r; a.I = i;
}
__device__ __forceinline__ float2 cm(float2 a, float2 b) {
    return make_float2(fmaf(a.x, b.x, -a.y * b.y), fmaf(a.x, b.y, a.y * b.x));
}

template<int K> __device__ __forceinline__ void rx_stage8(C2* v, float2 cs) {
    ull cc = dup2(cs.x), ss = dup2(cs.y), ns = dup2(-cs.y);
#pragma unroll
    for (int p = 0; p < 4; ++p) {
        int i0 = ((p >> K) << (K + 1)) | (p & ((1 << K) - 1));
        rx_bfly(v[i0], v[i0 | (1 << K)], cc, ss, ns);
    }
}
template<int K> __device__ __forceinline__ void h_stage8(C2* v) {
    const float r2 = 0.7071067811865476f;
    ull rr = dup2(r2), nr = dup2(-r2);
#pragma unroll
    for (int p = 0; p < 4; ++p) {
        int i0 = ((p >> K) << (K + 1)) | (p & ((1 << K) - 1));
        h_bfly(v[i0], v[i0 | (1 << K)], rr, nr);
    }
}
__device__ __forceinline__ void h3(C2* v) { h_stage8<0>(v); h_stage8<1>(v); h_stage8<2>(v); }
__device__ __forceinline__ void rx3(C2* v, int l, int b0) {
    rx_stage8<0>(v, g_cs[l * 32 + b0 + 0]);
    rx_stage8<1>(v, g_cs[l * 32 + b0 + 1]);
    rx_stage8<2>(v, g_cs[l * 32 + b0 + 2]);
}

// smem swizzle: conflict-free per 8-lane phase for all access patterns used
__device__ __forceinline__ unsigned sw(unsigned t) { return t ^ ((t >> 3) & 7u); }

// cis( sum_k ±hz[l,b0+k] ) with sign from bit k of e
__device__ __forceinline__ float2 cis_bits(int l, int b0, int nb, int e) {
    float ph = 0.f;
    for (int k = 0; k < nb; ++k) {
        float t = g_hz[l * 32 + b0 + k];
        ph += ((e >> k) & 1) ? t : -t;
    }
    float s, c; sincosf(ph, &s, &c);
    return make_float2(c, s);
}

// Setup: per (layer, bit) RX coefs + RZ half angles (theta index = l*20 + (19-bit))
__global__ void k_setup(const float* __restrict__ thx, const float* __restrict__ thz) {
    int i = threadIdx.x;
    if (i < 80) {
        int l = i / 20, q = i % 20, bit = 19 - q;
        float s, c; sincosf(0.5f * thx[i], &s, &c);
        g_cs[l * 32 + bit] = make_float2(c, s);
        g_hz[l * 32 + bit] = 0.5f * thz[i];
    }
}

// ---------------------------------------------------------------------------
// LOW pass: tile = state bits 0..10 (2048 elems, 32KB), 256 thr x 8 elems.
// Rounds gate bits 0..2 | 3..5 | 6..8 | 9..10, with RZ(0..10) via cis tables.
// HG: layer-0 (H then per-round phase then RX). Else: full phase in R0, RX only.
// FO: final gray-decode scatter of REAL parts into fout.
// src: 1 -> in=B,out=A ; 0 -> in=A,out=B.
// ---------------------------------------------------------------------------
template<bool HG, bool PL, bool FO>
__global__ void __launch_bounds__(256) k_low(
    const float* __restrict__ re, const float* __restrict__ im,
    int src, float* __restrict__ fout, int l)
{
    __shared__ ulonglong2 ts[2048];
    __shared__ float2 z0[8], z1[8], z2[8], z3[4];
    const unsigned u = threadIdx.x, blk = blockIdx.x;
    const unsigned pair = blk >> 9, base = (blk & 511u) << 11;   // bits 11..19
    const size_t poff = (size_t)pair << NQ;

    const ulonglong2* __restrict__ in = (src & 1) ? g_bufB : g_bufA;
    ulonglong2* __restrict__ out = (src & 1) ? g_bufA : g_bufB;

    if (u < 8)       z0[u]      = cis_bits(l, 0, 3, u);
    else if (u < 16) z1[u - 8]  = cis_bits(l, 3, 3, u - 8);
    else if (u < 24) z2[u - 16] = cis_bits(l, 6, 3, u - 16);
    else if (u < 28) z3[u - 24] = cis_bits(l, 9, 2, u - 24);
    __syncthreads();

    C2 v[8];
    // R0: e = bits 0..2
    {
        const unsigned t0 = u << 3;
        if (PL) {
            size_t b0 = ((size_t)(2 * pair) << NQ) + base + t0;
            const float4* r0p = (const float4*)(re + b0);
            const float4* r1p = (const float4*)(re + b0 + NSTATE);
            const float4* i0p = (const float4*)(im + b0);
            const float4* i1p = (const float4*)(im + b0 + NSTATE);
#pragma unroll
            for (int j = 0; j < 2; ++j) {
                float4 ra = r0p[j], rb = r1p[j], ia = i0p[j], ib = i1p[j];
                v[4 * j + 0].R = pk2(ra.x, rb.x); v[4 * j + 0].I = pk2(ia.x, ib.x);
                v[4 * j + 1].R = pk2(ra.y, rb.y); v[4 * j + 1].I = pk2(ia.y, ib.y);
                v[4 * j + 2].R = pk2(ra.z, rb.z); v[4 * j + 2].I = pk2(ia.z, ib.z);
                v[4 * j + 3].R = pk2(ra.w, rb.w); v[4 * j + 3].I = pk2(ia.w, ib.w);
            }
        } else {
#pragma unroll
            for (int e = 0; e < 8; ++e) {
                ulonglong2 w = in[poff + base + t0 + e]; v[e].R = w.x; v[e].I = w.y;
            }
        }
        if (HG) {
            h3(v);
#pragma unroll
            for (int e = 0; e < 8; ++e) phf(v[e], z0[e]);
        } else {
            float2 thrf = cm(cm(z1[u & 7], z2[(u >> 3) & 7]), z3[u >> 6]);
#pragma unroll
            for (int e = 0; e < 8; ++e) phf(v[e], cm(thrf, z0[e]));
        }
        rx3(v, l, 0);
#pragma unroll
        for (int e = 0; e < 8; ++e) ts[sw(t0 | e)] = make_ulonglong2(v[e].R, v[e].I);
    }
    __syncthreads();
    // R1: e = bits 3..5
    {
        const unsigned tb = ((u >> 3) << 6) | (u & 7u);
#pragma unroll
        for (int e = 0; e < 8; ++e) { ulonglong2 w = ts[sw(tb | (e << 3))]; v[e].R = w.x; v[e].I = w.y; }
        if (HG) {
            h3(v);
#pragma unroll
            for (int e = 0; e < 8; ++e) phf(v[e], z1[e]);
        }
        rx3(v, l, 3);
#pragma unroll
        for (int e = 0; e < 8; ++e) ts[sw(tb | (e << 3))] = make_ulonglong2(v[e].R, v[e].I);
    }
    __syncthreads();
    // R2: e = bits 6..8
    {
        const unsigned tb = ((u >> 6) << 9) | (u & 63u);
#pragma unroll
        for (int e = 0; e < 8; ++e) { ulonglong2 w = ts[sw(tb | (e << 6))]; v[e].R = w.x; v[e].I = w.y; }
        if (HG) {
            h3(v);
#pragma unroll
            for (int e = 0; e < 8; ++e) phf(v[e], z2[e]);
        }
        rx3(v, l, 6);
#pragma unroll
        for (int e = 0; e < 8; ++e) ts[sw(tb | (e << 6))] = make_ulonglong2(v[e].R, v[e].I);
    }
    __syncthreads();
    // R3: e = bits 8..10 (bit 8 gated in R2); gates on bits 9,10
    {
#pragma unroll
        for (int e = 0; e < 8; ++e) { ulonglong2 w = ts[sw((e << 8) | u)]; v[e].R = w.x; v[e].I = w.y; }
        if (HG) {
            h_stage8<1>(v); h_stage8<2>(v);
#pragma unroll
            for (int e = 0; e < 8; ++e) phf(v[e], z3[e >> 1]);
        } else {
            ;
        }
        rx_stage8<1>(v, g_cs[l * 32 + 9]);
        rx_stage8<2>(v, g_cs[l * 32 + 10]);
        if (FO) {
            // out[i] = Re(state[i ^ (i>>1)])  <=>  fout[graydecode(s)] = Re(state[s])
#pragma unroll
            for (int e = 0; e < 8; ++e) {
                unsigned s = base | ((unsigned)e << 8) | u;
                unsigned d = s; d ^= d >> 1; d ^= d >> 2; d ^= d >> 4; d ^= d >> 8; d ^= d >> 16;
                float lo, hi; upk2(v[e].R, lo, hi);
                fout[((size_t)(2 * pair) << NQ) + d] = lo;
                fout[((size_t)(2 * pair + 1) << NQ) + d] = hi;
            }
        } else {
#pragma unroll
            for (int e = 0; e < 8; ++e)
                out[poff + base + ((unsigned)e << 8) + u] = make_ulonglong2(v[e].R, v[e].I);
        }
    }
}

// ---------------------------------------------------------------------------
// HIGH first (layer 0): H(11..19) + RZ0(11..19) + RX0(11..19), 3 rounds.
// Tile local bits {0,1} U {11..19}; block fixes bits 2..10.
// ---------------------------------------------------------------------------
__global__ void __launch_bounds__(256) k_highf(int src, int l)
{
    __shared__ ulonglong2 ts[2048];
    __shared__ float2 zh0[8], zh1[8], zh2[8];
    const unsigned u = threadIdx.x, blk = blockIdx.x;
    const unsigned pair = blk >> 9, mid = (blk & 511u) << 2;   // state bits 2..10
    const size_t poff = (size_t)pair << NQ;

    const ulonglong2* __restrict__ in = (src & 1) ? g_bufB : g_bufA;
    ulonglong2* __restrict__ out = (src & 1) ? g_bufA : g_bufB;

    if (u < 8)       zh0[u]      = cis_bits(l, 11, 3, u);
    else if (u < 16) zh1[u - 8]  = cis_bits(l, 14, 3, u - 8);
    else if (u < 24) zh2[u - 16] = cis_bits(l, 17, 3, u - 16);
    __syncthreads();

    C2 v[8];
    const unsigned low2 = u & 3u, hi6 = u >> 2;
    const unsigned gfix = (hi6 << 14) | mid | low2;

    // R0: e = bits 11..13 : H + phase + RX
    {
#pragma unroll
        for (int e = 0; e < 8; ++e) {
            ulonglong2 w = in[poff + (gfix | ((unsigned)e << 11))]; v[e].R = w.x; v[e].I = w.y;
        }
        h3(v);
#pragma unroll
        for (int e = 0; e < 8; ++e) phf(v[e], zh0[e]);
        rx3(v, l, 11);
        const unsigned tb = (hi6 << 5) | low2;
#pragma unroll
        for (int e = 0; e < 8; ++e) ts[sw(tb | (e << 2))] = make_ulonglong2(v[e].R, v[e].I);
    }
    __syncthreads();
    // R1: e = bits 14..16
    {
        const unsigned tb = ((u >> 5) << 8) | (u & 31u);
#pragma unroll
        for (int e = 0; e < 8; ++e) { ulonglong2 w = ts[sw(tb | (e << 5))]; v[e].R = w.x; v[e].I = w.y; }
        h3(v);
#pragma unroll
        for (int e = 0; e < 8; ++e) phf(v[e], zh1[e]);
        rx3(v, l, 14);
#pragma unroll
        for (int e = 0; e < 8; ++e) ts[sw(tb | (e << 5))] = make_ulonglong2(v[e].R, v[e].I);
    }
    __syncthreads();
    // R2: e = bits 17..19, store linear
    {
#pragma unroll
        for (int e = 0; e < 8; ++e) { ulonglong2 w = ts[sw((e << 8) | u)]; v[e].R = w.x; v[e].I = w.y; }
        h3(v);
#pragma unroll
        for (int e = 0; e < 8; ++e) phf(v[e], zh2[e]);
        rx3(v, l, 17);
        const unsigned gl = mid | (u & 3u) | (((u >> 2) & 63u) << 11);
#pragma unroll
        for (int e = 0; e < 8; ++e)
            out[poff + (gl | ((unsigned)e << 17))] = make_ulonglong2(v[e].R, v[e].I);
    }
}

// ---------------------------------------------------------------------------
// HIGH mid (layers 1..3): gray gather (fused CNOT chain of prev layer) +
// RZ_l(11..19) + RX_l(11..19). Full local phase applied in R0 via tables.
// ---------------------------------------------------------------------------
__global__ void __launch_bounds__(256) k_highm(int src, int l)
{
    __shared__ ulonglong2 ts[2048];
    __shared__ float2 zh0[8], zh1[8], zh2[8];
    const unsigned u = threadIdx.x, blk = blockIdx.x;
    const unsigned pair = blk >> 9, mid = (blk & 511u) << 2;   // state bits 2..10
    const size_t poff = (size_t)pair << NQ;

    const ulonglong2* __restrict__ in = (src & 1) ? g_bufB : g_bufA;
    ulonglong2* __restrict__ out = (src & 1) ? g_bufA : g_bufB;

    if (u < 8)       zh0[u]      = cis_bits(l, 11, 3, u);
    else if (u < 16) zh1[u - 8]  = cis_bits(l, 14, 3, u - 8);
    else if (u < 24) zh2[u - 16] = cis_bits(l, 17, 3, u - 16);
    __syncthreads();

    C2 v[8];
    const unsigned low2 = u & 3u, hi6 = u >> 2;
    const unsigned gfix = (hi6 << 14) | mid | low2;

    // R0: e = bits 11..13 : gray gather + RZ(11..19) + RX(11..13)
    {
        float2 thrf = cm(zh1[hi6 & 7], zh2[hi6 >> 3]);
#pragma unroll
        for (int e = 0; e < 8; ++e) {
            unsigned g = gfix | ((unsigned)e << 11);
            unsigned a = g ^ (g >> 1);               // CNOT chain = binary->gray
            ulonglong2 w = in[poff + a]; v[e].R = w.x; v[e].I = w.y;
            phf(v[e], cm(thrf, zh0[e]));
        }
        rx3(v, l, 11);
        const unsigned tb = (hi6 << 5) | low2;
#pragma unroll
        for (int e = 0; e < 8; ++e) ts[sw(tb | (e << 2))] = make_ulonglong2(v[e].R, v[e].I);
    }
    __syncthreads();
    // R1: e = bits 14..16 : RX
    {
        const unsigned tb = ((u >> 5) << 8) | (u & 31u);
#pragma unroll
        for (int e = 0; e < 8; ++e) { ulonglong2 w = ts[sw(tb | (e << 5))]; v[e].R = w.x; v[e].I = w.y; }
        rx3(v, l, 14);
#pragma unroll
        for (int e = 0; e < 8; ++e) ts[sw(tb | (e << 5))] = make_ulonglong2(v[e].R, v[e].I);
    }
    __syncthreads();
    // R2: e = bits 17..19 : RX, store linear
    {
#pragma unroll
        for (int e = 0; e < 8; ++e) { ulonglong2 w = ts[sw((e << 8) | u)]; v[e].R = w.x; v[e].I = w.y; }
        rx3(v, l, 17);
        const unsigned gl = mid | (u & 3u) | (((u >> 2) & 63u) << 11);
#pragma unroll
        for (int e = 0; e < 8; ++e)
            out[poff + (gl | ((unsigned)e << 17))] = make_ulonglong2(v[e].R, v[e].I);
    }
}

extern "C" void kernel_launch(void* const* d_in, const int* in_sizes, int n_in,
                              void* d_out, int out_size) {
    const float *re = nullptr, *im = nullptr, *thx = nullptr, *thz = nullptr;
    for (int i = 0; i < n_in; ++i) {
        if (in_sizes[i] > 1024) {
            if (!re) re = (const float*)d_in[i];
            else if (!im) im = (const float*)d_in[i];
        } else {
            if (!thx) thx = (const float*)d_in[i];
            else if (!thz) thz = (const float*)d_in[i];
        }
    }
    if (!re || !im || !thx || !thz) return;

    const dim3 gr(NPAIR * 512);
    const int th = 256;

    k_setup<<<1, 128>>>(thx, thz);
    // P1: low  : H+RZ0+RX0 (bits 0..10), planar -> A     (src=1 => out=A)
    k_low<true, true, false><<<gr, th>>>(re, im, 1, nullptr, 0);
    // P2: high : H+RZ0+RX0 (bits 11..19)        A -> B
    k_highf<<<gr, th>>>(0, 0);
    // P3: high : gray0 + RZ1+RX1 (hi)           B -> A
    k_highm<<<gr, th>>>(1, 1);
    // P4: low  : RZ1+RX1 (lo)                   A -> B
    k_low<false, false, false><<<gr, th>>>(nullptr, nullptr, 0, nullptr, 1);
    // P5: high : gray1 + RZ2+RX2 (hi)           B -> A
    k_highm<<<gr, th>>>(1, 2);
    // P6: low  : RZ2+RX2 (lo)                   A -> B
    k_low<false, false, false><<<gr, th>>>(nullptr, nullptr, 0, nullptr, 2);
    // P7: high : gray2 + RZ3+RX3 (hi)           B -> A
    k_highm<<<gr, th>>>(1, 3);
    // P8: low  : RZ3+RX3 (lo) + gray3 scatter of REAL parts -> d_out
    k_low<false, false, true><<<gr, th>>>(nullptr, nullptr, 0, (float*)d_out, 3);
}

// round 11
// speedup vs baseline: 1.2392x; 1.1446x over previous
#include <cuda_runtime.h>
#include <math.h>

#define NQ 20
#define NSTATE (1u << NQ)
#define NPAIR 2   // batch pairs (B=4 -> 2 pairs packed into f32x2 lanes)
typedef unsigned long long ull;

// Scratch state, batch-pair packed: element = ulonglong2{ R=(re_b0,re_b1), I=(im_b0,im_b1) }
__device__ __align__(16) ulonglong2 g_bufA[(size_t)NPAIR << NQ];
__device__ __align__(16) ulonglong2 g_bufB[(size_t)NPAIR << NQ];
// Precomputed per (layer, state-bit): RX (cos(t/2), sin(t/2)) and RZ half-angles
__device__ float2 g_cs[4 * 32];
__device__ float  g_hz[4 * 32];

struct C2 { ull R, I; };

__device__ __forceinline__ ull pk2(float lo, float hi) {
    ull r; asm("mov.b64 %0,{%1,%2};" : "=l"(r) : "f"(lo), "f"(hi)); return r;
}
__device__ __forceinline__ void upk2(ull v, float& lo, float& hi) {
    asm("mov.b64 {%0,%1},%2;" : "=f"(lo), "=f"(hi) : "l"(v));
}
__device__ __forceinline__ ull dup2(float x) { return pk2(x, x); }
__device__ __forceinline__ ull f2mul(ull a, ull b) {
    ull r; asm("mul.rn.f32x2 %0,%1,%2;" : "=l"(r) : "l"(a), "l"(b)); return r;
}
__device__ __forceinline__ ull f2fma(ull a, ull b, ull c) {
    ull r; asm("fma.rn.f32x2 %0,%1,%2,%3;" : "=l"(r) : "l"(a), "l"(b), "l"(c)); return r;
}

// RX butterfly: v0' = c v0 - i s v1 ; v1' = -i s v0 + c v1
__device__ __forceinline__ void rx_bfly(C2& a, C2& b, ull cc, ull ss, ull ns) {
    ull r0 = f2fma(a.R, cc, f2mul(b.I, ss));
    ull i0 = f2fma(a.I, cc, f2mul(b.R, ns));
    ull r1 = f2fma(b.R, cc, f2mul(a.I, ss));
    ull i1 = f2fma(b.I, cc, f2mul(a.R, ns));
    a.R = r0; a.I = i0; b.R = r1; b.I = i1;
}
__device__ __forceinline__ void h_bfly(C2& a, C2& b, ull rr, ull nr) {
    ull r0 = f2fma(a.R, rr, f2mul(b.R, rr));
    ull i0 = f2fma(a.I, rr, f2mul(b.I, rr));
    ull r1 = f2fma(a.R, rr, f2mul(b.R, nr));
    ull i1 = f2fma(a.I, rr, f2mul(b.I, nr));
    a.R = r0; a.I = i0; b.R = r1; b.I = i1;
}
// v *= (f.x + i f.y)
__device__ __forceinline__ void phf(C2& a, float2 f) {
    ull cc = dup2(f.x), ss = dup2(f.y), ns = dup2(-f.y);
    ull r = f2fma(a.R, cc, f2mul(a.I, ns));
    ull i = f2fma(a.I, cc, f2mul(a.R, ss));
    a.R = r; a.I = i;
}
__device__ __forceinline__ float2 cm(float2 a, float2 b) {
    return make_float2(fmaf(a.x, b.x, -a.y * b.y), fmaf(a.x, b.y, a.y * b.x));
}

template<int K> __device__ __forceinline__ void rx_stage8(C2* v, float2 cs) {
    ull cc = dup2(cs.x), ss = dup2(cs.y), ns = dup2(-cs.y);
#pragma unroll
    for (int p = 0; p < 4; ++p) {
        int i0 = ((p >> K) << (K + 1)) | (p & ((1 << K) - 1));
        rx_bfly(v[i0], v[i0 | (1 << K)], cc, ss, ns);
    }
}
template<int K> __device__ __forceinline__ void h_stage8(C2* v) {
    const float r2 = 0.7071067811865476f;
    ull rr = dup2(r2), nr = dup2(-r2);
#pragma unroll
    for (int p = 0; p < 4; ++p) {
        int i0 = ((p >> K) << (K + 1)) | (p & ((1 << K) - 1));
        h_bfly(v[i0], v[i0 | (1 << K)], rr, nr);
    }
}
__device__ __forceinline__ void h3(C2* v) { h_stage8<0>(v); h_stage8<1>(v); h_stage8<2>(v); }
__device__ __forceinline__ void rx3(C2* v, int l, int b0) {
    rx_stage8<0>(v, g_cs[l * 32 + b0 + 0]);
    rx_stage8<1>(v, g_cs[l * 32 + b0 + 1]);
    rx_stage8<2>(v, g_cs[l * 32 + b0 + 2]);
}

// smem swizzle: conflict-free per 8-lane phase for all access patterns used
__device__ __forceinline__ unsigned sw(unsigned t) { return t ^ ((t >> 3) & 7u); }

// cis( sum_k ±hz[l,b0+k] ) with sign from bit k of e
__device__ __forceinline__ float2 cis_bits(int l, int b0, int nb, int e) {
    float ph = 0.f;
    for (int k = 0; k < nb; ++k) {
        float t = g_hz[l * 32 + b0 + k];
        ph += ((e >> k) & 1) ? t : -t;
    }
    float s, c; sincosf(ph, &s, &c);
    return make_float2(c, s);
}

// Setup: per (layer, bit) RX coefs + RZ half angles (theta index = l*20 + (19-bit))
__global__ void k_setup(const float* __restrict__ thx, const float* __restrict__ thz) {
    int i = threadIdx.x;
    if (i < 80) {
        int l = i / 20, q = i % 20, bit = 19 - q;
        float s, c; sincosf(0.5f * thx[i], &s, &c);
        g_cs[l * 32 + bit] = make_float2(c, s);
        g_hz[l * 32 + bit] = 0.5f * thz[i];
    }
}

// ---------------------------------------------------------------------------
// LOW pass: tile = state bits 0..10 (2048 elems, 32KB), 256 thr x 8 elems.
// Round order chosen for COALESCED global access:
//   R0: e = bits 8..10 (global load [.. (e<<8)+u] is lane-contiguous), gates 8..10
//   R1: e = bits 0..2,  gates 0..2
//   R2: e = bits 3..5,  gates 3..5
//   R3: e = bits 6..8 (gates 6..7 only), store [.. (e<<6)+(u&63)..] lane-contiguous
// HG: layer-0 (H then per-round phase slice then RX). Else full local phase in R0.
// FO: final gray-decode scatter of REAL parts into fout (warp-contiguous).
// src: 1 -> in=B,out=A ; 0 -> in=A,out=B.
// ---------------------------------------------------------------------------
template<bool HG, bool PL, bool FO>
__global__ void __launch_bounds__(256, 5) k_low(
    const float* __restrict__ re, const float* __restrict__ im,
    int src, float* __restrict__ fout, int l)
{
    __shared__ ulonglong2 ts[2048];
    __shared__ float2 z0[8], z1[8], z8[8], z67[4];
    const unsigned u = threadIdx.x, blk = blockIdx.x;
    const unsigned pair = blk >> 9, base = (blk & 511u) << 11;   // bits 11..19
    const size_t poff = (size_t)pair << NQ;

    const ulonglong2* __restrict__ in = (src & 1) ? g_bufB : g_bufA;
    ulonglong2* __restrict__ out = (src & 1) ? g_bufA : g_bufB;

    if (u < 8)       z0[u]       = cis_bits(l, 0, 3, u);
    else if (u < 16) z1[u - 8]   = cis_bits(l, 3, 3, u - 8);
    else if (u < 24) z8[u - 16]  = cis_bits(l, 8, 3, u - 16);
    else if (u < 28) z67[u - 24] = cis_bits(l, 6, 2, u - 24);
    __syncthreads();

    C2 v[8];
    // R0: e = bits 8..10 (coalesced global load); gates 8,9,10
    {
        if (PL) {
            size_t b0 = ((size_t)(2 * pair) << NQ) + base + u;
#pragma unroll
            for (int e = 0; e < 8; ++e) {
                size_t idx = b0 + ((size_t)e << 8);
                v[e].R = pk2(re[idx], re[idx + NSTATE]);
                v[e].I = pk2(im[idx], im[idx + NSTATE]);
            }
        } else {
#pragma unroll
            for (int e = 0; e < 8; ++e) {
                ulonglong2 w = in[poff + base + ((unsigned)e << 8) + u];
                v[e].R = w.x; v[e].I = w.y;
            }
        }
        if (HG) {
            h3(v);
#pragma unroll
            for (int e = 0; e < 8; ++e) phf(v[e], z8[e]);
        } else {
            float2 thrf = cm(cm(z0[u & 7], z1[(u >> 3) & 7]), z67[(u >> 6) & 3]);
#pragma unroll
            for (int e = 0; e < 8; ++e) phf(v[e], cm(thrf, z8[e]));
        }
        rx3(v, l, 8);
#pragma unroll
        for (int e = 0; e < 8; ++e) ts[sw((e << 8) | u)] = make_ulonglong2(v[e].R, v[e].I);
    }
    __syncthreads();
    // R1: e = bits 0..2 ; thread u = bits 3..10
    {
        const unsigned tb = u << 3;
#pragma unroll
        for (int e = 0; e < 8; ++e) { ulonglong2 w = ts[sw(tb | e)]; v[e].R = w.x; v[e].I = w.y; }
        if (HG) {
            h3(v);
#pragma unroll
            for (int e = 0; e < 8; ++e) phf(v[e], z0[e]);
        }
        rx3(v, l, 0);
#pragma unroll
        for (int e = 0; e < 8; ++e) ts[sw(tb | e)] = make_ulonglong2(v[e].R, v[e].I);
    }
    __syncthreads();
    // R2: e = bits 3..5 ; thread: bits 0..2 = u&7, bits 6..10 = u>>3
    {
        const unsigned tb = ((u >> 3) << 6) | (u & 7u);
#pragma unroll
        for (int e = 0; e < 8; ++e) { ulonglong2 w = ts[sw(tb | (e << 3))]; v[e].R = w.x; v[e].I = w.y; }
        if (HG) {
            h3(v);
#pragma unroll
            for (int e = 0; e < 8; ++e) phf(v[e], z1[e]);
        }
        rx3(v, l, 3);
#pragma unroll
        for (int e = 0; e < 8; ++e) ts[sw(tb | (e << 3))] = make_ulonglong2(v[e].R, v[e].I);
    }
    __syncthreads();
    // R3: e = bits 6..8 (bit 8 gated in R0); gates 6,7; coalesced store
    {
        const unsigned tb = ((u >> 6) << 9) | (u & 63u);
#pragma unroll
        for (int e = 0; e < 8; ++e) { ulonglong2 w = ts[sw(tb | (e << 6))]; v[e].R = w.x; v[e].I = w.y; }
        if (HG) {
            h_stage8<0>(v); h_stage8<1>(v);
#pragma unroll
            for (int e = 0; e < 8; ++e) phf(v[e], z67[e & 3]);
        }
        rx_stage8<0>(v, g_cs[l * 32 + 6]);
        rx_stage8<1>(v, g_cs[l * 32 + 7]);
        if (FO) {
            // out[i] = Re(state[i ^ (i>>1)])  <=>  fout[graydecode(s)] = Re(state[s])
#pragma unroll
            for (int e = 0; e < 8; ++e) {
                unsigned s = base | tb | ((unsigned)e << 6);
                unsigned d = s; d ^= d >> 1; d ^= d >> 2; d ^= d >> 4; d ^= d >> 8; d ^= d >> 16;
                float lo, hi; upk2(v[e].R, lo, hi);
                fout[((size_t)(2 * pair) << NQ) + d] = lo;
                fout[((size_t)(2 * pair + 1) << NQ) + d] = hi;
            }
        } else {
#pragma unroll
            for (int e = 0; e < 8; ++e)
                out[poff + base + tb + ((unsigned)e << 6)] = make_ulonglong2(v[e].R, v[e].I);
        }
    }
}

// ---------------------------------------------------------------------------
// HIGH first (layer 0): H(11..19) + RZ0(11..19) + RX0(11..19), 3 rounds.
// Tile local bits {0,1} U {11..19}; block fixes bits 2..10.
// ---------------------------------------------------------------------------
__global__ void __launch_bounds__(256, 5) k_highf(int src, int l)
{
    __shared__ ulonglong2 ts[2048];
    __shared__ float2 zh0[8], zh1[8], zh2[8];
    const unsigned u = threadIdx.x, blk = blockIdx.x;
    const unsigned pair = blk >> 9, mid = (blk & 511u) << 2;   // state bits 2..10
    const size_t poff = (size_t)pair << NQ;

    const ulonglong2* __restrict__ in = (src & 1) ? g_bufB : g_bufA;
    ulonglong2* __restrict__ out = (src & 1) ? g_bufA : g_bufB;

    if (u < 8)       zh0[u]      = cis_bits(l, 11, 3, u);
    else if (u < 16) zh1[u - 8]  = cis_bits(l, 14, 3, u - 8);
    else if (u < 24) zh2[u - 16] = cis_bits(l, 17, 3, u - 16);
    __syncthreads();

    C2 v[8];
    const unsigned low2 = u & 3u, hi6 = u >> 2;
    const unsigned gfix = (hi6 << 14) | mid | low2;

    // R0: e = bits 11..13 : H + phase + RX
    {
#pragma unroll
        for (int e = 0; e < 8; ++e) {
            ulonglong2 w = in[poff + (gfix | ((unsigned)e << 11))]; v[e].R = w.x; v[e].I = w.y;
        }
        h3(v);
#pragma unroll
        for (int e = 0; e < 8; ++e) phf(v[e], zh0[e]);
        rx3(v, l, 11);
        const unsigned tb = (hi6 << 5) | low2;
#pragma unroll
        for (int e = 0; e < 8; ++e) ts[sw(tb | (e << 2))] = make_ulonglong2(v[e].R, v[e].I);
    }
    __syncthreads();
    // R1: e = bits 14..16
    {
        const unsigned tb = ((u >> 5) << 8) | (u & 31u);
#pragma unroll
        for (int e = 0; e < 8; ++e) { ulonglong2 w = ts[sw(tb | (e << 5))]; v[e].R = w.x; v[e].I = w.y; }
        h3(v);
#pragma unroll
        for (int e = 0; e < 8; ++e) phf(v[e], zh1[e]);
        rx3(v, l, 14);
#pragma unroll
        for (int e = 0; e < 8; ++e) ts[sw(tb | (e << 5))] = make_ulonglong2(v[e].R, v[e].I);
    }
    __syncthreads();
    // R2: e = bits 17..19, store linear
    {
#pragma unroll
        for (int e = 0; e < 8; ++e) { ulonglong2 w = ts[sw((e << 8) | u)]; v[e].R = w.x; v[e].I = w.y; }
        h3(v);
#pragma unroll
        for (int e = 0; e < 8; ++e) phf(v[e], zh2[e]);
        rx3(v, l, 17);
        const unsigned gl = mid | (u & 3u) | (((u >> 2) & 63u) << 11);
#pragma unroll
        for (int e = 0; e < 8; ++e)
            out[poff + (gl | ((unsigned)e << 17))] = make_ulonglong2(v[e].R, v[e].I);
    }
}

// ---------------------------------------------------------------------------
// HIGH mid (layers 1..3): gray gather (fused CNOT chain of prev layer) +
// RZ_l(11..19) + RX_l(11..19). Full local phase applied in R0 via tables.
// ---------------------------------------------------------------------------
__global__ void __launch_bounds__(256, 5) k_highm(int src, int l)
{
    __shared__ ulonglong2 ts[2048];
    __shared__ float2 zh0[8], zh1[8], zh2[8];
    const unsigned u = threadIdx.x, blk = blockIdx.x;
    const unsigned pair = blk >> 9, mid = (blk & 511u) << 2;   // state bits 2..10
    const size_t poff = (size_t)pair << NQ;

    const ulonglong2* __restrict__ in = (src & 1) ? g_bufB : g_bufA;
    ulonglong2* __restrict__ out = (src & 1) ? g_bufA : g_bufB;

    if (u < 8)       zh0[u]      = cis_bits(l, 11, 3, u);
    else if (u < 16) zh1[u - 8]  = cis_bits(l, 14, 3, u - 8);
    else if (u < 24) zh2[u - 16] = cis_bits(l, 17, 3, u - 16);
    __syncthreads();

    C2 v[8];
    const unsigned low2 = u & 3u, hi6 = u >> 2;
    const unsigned gfix = (hi6 << 14) | mid | low2;

    // R0: e = bits 11..13 : gray gather + RZ(11..19) + RX(11..13)
    {
        float2 thrf = cm(zh1[hi6 & 7], zh2[hi6 >> 3]);
#pragma unroll
        for (int e = 0; e < 8; ++e) {
            unsigned g = gfix | ((unsigned)e << 11);
            unsigned a = g ^ (g >> 1);               // CNOT chain = binary->gray
            ulonglong2 w = in[poff + a]; v[e].R = w.x; v[e].I = w.y;
            phf(v[e], cm(thrf, zh0[e]));
        }
        rx3(v, l, 11);
        const unsigned tb = (hi6 << 5) | low2;
#pragma unroll
        for (int e = 0; e < 8; ++e) ts[sw(tb | (e << 2))] = make_ulonglong2(v[e].R, v[e].I);
    }
    __syncthreads();
    // R1: e = bits 14..16 : RX
    {
        const unsigned tb = ((u >> 5) << 8) | (u & 31u);
#pragma unroll
        for (int e = 0; e < 8; ++e) { ulonglong2 w = ts[sw(tb | (e << 5))]; v[e].R = w.x; v[e].I = w.y; }
        rx3(v, l, 14);
#pragma unroll
        for (int e = 0; e < 8; ++e) ts[sw(tb | (e << 5))] = make_ulonglong2(v[e].R, v[e].I);
    }
    __syncthreads();
    // R2: e = bits 17..19 : RX, store linear
    {
#pragma unroll
        for (int e = 0; e < 8; ++e) { ulonglong2 w = ts[sw((e << 8) | u)]; v[e].R = w.x; v[e].I = w.y; }
        rx3(v, l, 17);
        const unsigned gl = mid | (u & 3u) | (((u >> 2) & 63u) << 11);
#pragma unroll
        for (int e = 0; e < 8; ++e)
            out[poff + (gl | ((unsigned)e << 17))] = make_ulonglong2(v[e].R, v[e].I);
    }
}

extern "C" void kernel_launch(void* const* d_in, const int* in_sizes, int n_in,
                              void* d_out, int out_size) {
    const float *re = nullptr, *im = nullptr, *thx = nullptr, *thz = nullptr;
    for (int i = 0; i < n_in; ++i) {
        if (in_sizes[i] > 1024) {
            if (!re) re = (const float*)d_in[i];
            else if (!im) im = (const float*)d_in[i];
        } else {
            if (!thx) thx = (const float*)d_in[i];
            else if (!thz) thz = (const float*)d_in[i];
        }
    }
    if (!re || !im || !thx || !thz) return;

    const dim3 gr(NPAIR * 512);
    const int th = 256;

    k_setup<<<1, 128>>>(thx, thz);
    // P1: low  : H+RZ0+RX0 (bits 0..10), planar -> A     (src=1 => out=A)
    k_low<true, true, false><<<gr, th>>>(re, im, 1, nullptr, 0);
    // P2: high : H+RZ0+RX0 (bits 11..19)        A -> B
    k_highf<<<gr, th>>>(0, 0);
    // P3: high : gray0 + RZ1+RX1 (hi)           B -> A
    k_highm<<<gr, th>>>(1, 1);
    // P4: low  : RZ1+RX1 (lo)                   A -> B
    k_low<false, false, false><<<gr, th>>>(nullptr, nullptr, 0, nullptr, 1);
    // P5: high : gray1 + RZ2+RX2 (hi)           B -> A
    k_highm<<<gr, th>>>(1, 2);
    // P6: low  : RZ2+RX2 (lo)                   A -> B
    k_low<false, false, false><<<gr, th>>>(nullptr, nullptr, 0, nullptr, 2);
    // P7: high : gray2 + RZ3+RX3 (hi)           B -> A
    k_highm<<<gr, th>>>(1, 3);
    // P8: low  : RZ3+RX3 (lo) + gray3 scatter of REAL parts -> d_out
    k_low<false, false, true><<<gr, th>>>(nullptr, nullptr, 0, (float*)d_out, 3);
}